// round 9
// baseline (speedup 1.0000x reference)
#include <cuda_runtime.h>

// Fused PreNorm cross-attention (query-length-1 over m=16 neighbors), fp32.
// Persistent-CTA design: Wq+Wkv live in SMEM (loaded once), Wo lives in
// registers; grid-stride loop over the 65536 (b,n) points. Hot kv GEMM uses
// packed fma.rn.f32x2 (sm_103a FFMA2) for 2 MACs/lane/instr.

#define THREADS 256
#define DIMX 128
#define MROWS 16
#define YSTR 20   // transposed-yn row stride (floats), float4-aligned, odd/32 enough

// ---- smem layout (float indices) ----
#define OFF_WQ   0        // 16384  : Wq [128][128]
#define OFF_WKV  16384    // 32768  : Wkv [128][256]
#define OFF_KV   49152    // 4096   : kv result [16][256]; ALSO raw staging (2176 f)
#define OFF_YT   53248    // 2560   : yn transposed [128][YSTR]
#define OFF_XN   55808    // 128
#define OFF_XO   55936    // 128
#define OFF_Q    56064    // 128
#define OFF_AO   56192    // 128
#define OFF_AT   56320    // 64
#define OFF_BUF  56384    // 128
#define OFF_BO   56512    // 128
#define OFF_G    56640    // 128
#define OFF_B    56768    // 128
#define SMEM_FLOATS 56896 // 227584 bytes

__device__ __forceinline__ unsigned long long pk2(float v) {
    unsigned long long r;
    unsigned int b = __float_as_uint(v);
    asm("mov.b64 %0, {%1, %1};" : "=l"(r) : "r"(b));
    return r;
}
__device__ __forceinline__ void ffma2(unsigned long long& a,
                                      unsigned long long xv,
                                      unsigned long long wv) {
    asm("fma.rn.f32x2 %0, %1, %2, %0;" : "+l"(a) : "l"(xv), "l"(wv));
}
__device__ __forceinline__ float2 upk2(unsigned long long v) {
    unsigned int lo, hi;
    asm("mov.b64 {%0, %1}, %2;" : "=r"(lo), "=r"(hi) : "l"(v));
    return make_float2(__uint_as_float(lo), __uint_as_float(hi));
}

__global__ void __launch_bounds__(THREADS, 1)
ca_fused_kernel(const float* __restrict__ x,
                const float* __restrict__ y,
                const float* __restrict__ ln_g,
                const float* __restrict__ ln_b,
                const float* __restrict__ Wq,
                const float* __restrict__ Wkv,
                const float* __restrict__ Wo,
                const float* __restrict__ bo,
                float* __restrict__ out,
                int P)
{
    extern __shared__ float sm[];
    float* sWq  = sm + OFF_WQ;
    float* sWkv = sm + OFF_WKV;
    float* sKV  = sm + OFF_KV;
    float* sYT  = sm + OFF_YT;
    float* sXN  = sm + OFF_XN;
    float* sXO  = sm + OFF_XO;
    float* sQ   = sm + OFF_Q;
    float* sAO  = sm + OFF_AO;
    float* sAT  = sm + OFF_AT;
    float* sBUF = sm + OFF_BUF;
    float* sBO  = sm + OFF_BO;
    float* sG   = sm + OFF_G;
    float* sB   = sm + OFF_B;

    const int tid  = threadIdx.x;
    const int warp = tid >> 5;
    const int lane = tid & 31;
    const int rg   = tid >> 6;   // 0..3 : row group (4 rows of kv)
    const int cg   = tid & 63;   // 0..63: col group (4 cols of kv)
    const int jj   = tid & 127;  // output column for Wo GEMM
    const int hf   = tid >> 7;   // 0/1  : i-half for Wo GEMM

    // ---- load weights into SMEM (once) ----
    {
        const float4* s4 = (const float4*)Wq;
        float4* d4 = (float4*)sWq;
        for (int u = tid; u < 4096; u += THREADS) d4[u] = s4[u];
        const float4* s42 = (const float4*)Wkv;
        float4* d42 = (float4*)sWkv;
        for (int u = tid; u < 8192; u += THREADS) d42[u] = s42[u];
        if (tid < 128) { sBO[tid] = bo[tid]; sG[tid] = ln_g[tid]; sB[tid] = ln_b[tid]; }
    }
    // ---- Wo into registers: thread holds Wo[hf*64 + ii][jj], ii=0..63 ----
    float wo[64];
#pragma unroll
    for (int ii = 0; ii < 64; ++ii) wo[ii] = Wo[(hf * 64 + ii) * 128 + jj];

    __syncthreads();

    for (int pt = blockIdx.x; pt < P; pt += gridDim.x) {
        // ---- stage raw y (16x128) + x (128) into sKV region (coalesced f4) ----
        {
            const float4* y4 = (const float4*)y + (size_t)pt * 512;
            const float4* x4 = (const float4*)x + (size_t)pt * 32;
            float4* raw = (float4*)sKV;
            for (int u = tid; u < 544; u += THREADS)
                raw[u] = (u < 512) ? y4[u] : x4[u - 512];
        }
        __syncthreads();

        // ---- LayerNorm: 17 rows (16 y rows -> sYT transposed, row 16 = x -> sXN) ----
        for (int r = warp; r < 17; r += 8) {
            const float* row = sKV + r * 128;
            float v0 = row[lane], v1 = row[lane + 32], v2 = row[lane + 64], v3 = row[lane + 96];
            float s  = v0 + v1 + v2 + v3;
            float q2 = v0 * v0 + v1 * v1 + v2 * v2 + v3 * v3;
#pragma unroll
            for (int o = 16; o > 0; o >>= 1) {
                s  += __shfl_xor_sync(0xffffffffu, s,  o);
                q2 += __shfl_xor_sync(0xffffffffu, q2, o);
            }
            float mu  = s * (1.0f / 128.0f);
            float var = q2 * (1.0f / 128.0f) - mu * mu;
            float rs  = rsqrtf(var + 1e-5f);
            float vs[4] = {v0, v1, v2, v3};
            if (r < 16) {
#pragma unroll
                for (int k = 0; k < 4; ++k) {
                    int i = lane + k * 32;
                    sYT[i * YSTR + r] = (vs[k] - mu) * rs * sG[i] + sB[i];
                }
            } else {
#pragma unroll
                for (int k = 0; k < 4; ++k) {
                    int i = lane + k * 32;
                    sXN[i] = (vs[k] - mu) * rs * sG[i] + sB[i];
                    sXO[i] = vs[k];
                }
            }
        }
        __syncthreads();

        // ---- kv GEMM: yn[16,128] @ Wkv[128,256] -> sKV[16,256]  (packed f32x2) ----
        unsigned long long a00 = 0, a01 = 0, a10 = 0, a11 = 0;
        unsigned long long a20 = 0, a21 = 0, a30 = 0, a31 = 0;
        {
            const float* yt = sYT + rg * 4;
            const float* wk = sWkv + cg * 4;
#pragma unroll 4
            for (int i = 0; i < 128; ++i) {
                float4 yv = *(const float4*)(yt + i * YSTR);         // 4 rows, broadcast
                ulonglong2 wv = *(const ulonglong2*)(wk + i * 256);  // 4 cols as 2x f32x2
                unsigned long long p;
                p = pk2(yv.x); ffma2(a00, p, wv.x); ffma2(a01, p, wv.y);
                p = pk2(yv.y); ffma2(a10, p, wv.x); ffma2(a11, p, wv.y);
                p = pk2(yv.z); ffma2(a20, p, wv.x); ffma2(a21, p, wv.y);
                p = pk2(yv.w); ffma2(a30, p, wv.x); ffma2(a31, p, wv.y);
            }
        }
        {
            float* dst = sKV + (rg * 4) * 256 + cg * 4;
            float2 lo, hi;
            lo = upk2(a00); hi = upk2(a01); *(float4*)(dst)        = make_float4(lo.x, lo.y, hi.x, hi.y);
            lo = upk2(a10); hi = upk2(a11); *(float4*)(dst + 256)  = make_float4(lo.x, lo.y, hi.x, hi.y);
            lo = upk2(a20); hi = upk2(a21); *(float4*)(dst + 512)  = make_float4(lo.x, lo.y, hi.x, hi.y);
            lo = upk2(a30); hi = upk2(a31); *(float4*)(dst + 768)  = make_float4(lo.x, lo.y, hi.x, hi.y);
        }

        // ---- q GEMM: xn[128] @ Wq[128,128] ----
        if (tid < 128) {
            float a = 0.0f;
#pragma unroll 8
            for (int i = 0; i < 128; ++i) a = fmaf(sXN[i], sWq[i * 128 + tid], a);
            sQ[tid] = a;
        }
        __syncthreads();

        // ---- dots + softmax over m=16, per head (threads 0..63) ----
        if (tid < 64) {
            int h = tid >> 4, m = tid & 15;
            const float* kk = sKV + m * 256 + h * 32;  // k = cols [0,128)
            const float* qq = sQ + h * 32;
            float dsum = 0.0f;
#pragma unroll
            for (int dd = 0; dd < 8; ++dd) {
                float4 k4 = *(const float4*)(kk + dd * 4);
                float4 q4 = *(const float4*)(qq + dd * 4);
                dsum += k4.x * q4.x + k4.y * q4.y + k4.z * q4.z + k4.w * q4.w;
            }
            dsum *= 0.17677669529663687f;  // 32^-0.5
            float mx = dsum;
#pragma unroll
            for (int o = 8; o > 0; o >>= 1)
                mx = fmaxf(mx, __shfl_xor_sync(0xffffffffu, mx, o));
            float e = __expf(dsum - mx);
            float se = e;
#pragma unroll
            for (int o = 8; o > 0; o >>= 1)
                se += __shfl_xor_sync(0xffffffffu, se, o);
            sAT[tid] = e / se;
        }
        __syncthreads();

        // ---- attention output: ao[h,d] = sum_m attn[h,m] * v[m,h,d] ----
        if (tid < 128) {
            int h = tid >> 5, d = tid & 31;
            const float* vv = sKV + 128 + h * 32 + d;  // v = cols [128,256)
            const float* at = sAT + h * 16;
            float a = 0.0f;
#pragma unroll
            for (int m = 0; m < 16; ++m) a = fmaf(at[m], vv[m * 256], a);
            sAO[tid] = a;
        }
        __syncthreads();

        // ---- out GEMM: ao[128] @ Wo[128,128] + bo + x  (Wo in registers) ----
        {
            const float* ain = sAO + hf * 64;
            float p = 0.0f;
#pragma unroll
            for (int ii = 0; ii < 64; ++ii) p = fmaf(ain[ii], wo[ii], p);
            if (hf) sBUF[jj] = p;
            __syncthreads();
            if (!hf) out[(size_t)pt * 128 + jj] = p + sBUF[jj] + sBO[jj] + sXO[jj];
        }
        __syncthreads();  // protect sKV/sBUF before next point's staging
    }
}

extern "C" void kernel_launch(void* const* d_in, const int* in_sizes, int n_in,
                              void* d_out, int out_size) {
    const float* x    = (const float*)d_in[0];
    const float* y    = (const float*)d_in[1];
    const float* ln_g = (const float*)d_in[2];
    const float* ln_b = (const float*)d_in[3];
    const float* Wq   = (const float*)d_in[4];
    const float* Wkv  = (const float*)d_in[5];
    const float* Wo   = (const float*)d_in[6];
    const float* bo   = (const float*)d_in[7];
    float* out = (float*)d_out;

    const int P = in_sizes[0] / 128;  // total (b*n) points

    int dev = 0;
    cudaGetDevice(&dev);
    int sms = 0;
    cudaDeviceGetAttribute(&sms, cudaDevAttrMultiProcessorCount, dev);
    if (sms <= 0) sms = 148;

    const size_t smem_bytes = (size_t)SMEM_FLOATS * sizeof(float);  // 227584
    cudaFuncSetAttribute(ca_fused_kernel,
                         cudaFuncAttributeMaxDynamicSharedMemorySize,
                         (int)smem_bytes);

    ca_fused_kernel<<<sms, THREADS, smem_bytes>>>(
        x, y, ln_g, ln_b, Wq, Wkv, Wo, bo, out, P);
}

// round 10
// speedup vs baseline: 1.0040x; 1.0040x over previous
#include <cuda_runtime.h>

// Fused PreNorm cross-attention (query-length-1 over m=16 neighbors), fp32.
// Persistent-CTA design: Wq+Wkv live in SMEM (loaded once), Wo lives in
// registers; grid-stride loop over the 65536 (b,n) points. Hot kv GEMM uses
// packed fma.rn.f32x2 (sm_103a FFMA2) for 2 MACs/lane/instr.

#define THREADS 256
#define DIMX 128
#define MROWS 16
#define YSTR 20   // transposed-yn row stride (floats), float4-aligned, odd/32 enough

// ---- smem layout (float indices) ----
#define OFF_WQ   0        // 16384  : Wq [128][128]
#define OFF_WKV  16384    // 32768  : Wkv [128][256]
#define OFF_KV   49152    // 4096   : kv result [16][256]; ALSO raw staging (2176 f)
#define OFF_YT   53248    // 2560   : yn transposed [128][YSTR]
#define OFF_XN   55808    // 128
#define OFF_XO   55936    // 128
#define OFF_Q    56064    // 128
#define OFF_AO   56192    // 128
#define OFF_AT   56320    // 64
#define OFF_BUF  56384    // 128
#define OFF_BO   56512    // 128
#define OFF_G    56640    // 128
#define OFF_B    56768    // 128
#define SMEM_FLOATS 56896 // 227584 bytes

__device__ __forceinline__ unsigned long long pk2(float v) {
    unsigned long long r;
    unsigned int b = __float_as_uint(v);
    asm("mov.b64 %0, {%1, %1};" : "=l"(r) : "r"(b));
    return r;
}
__device__ __forceinline__ void ffma2(unsigned long long& a,
                                      unsigned long long xv,
                                      unsigned long long wv) {
    asm("fma.rn.f32x2 %0, %1, %2, %0;" : "+l"(a) : "l"(xv), "l"(wv));
}
__device__ __forceinline__ float2 upk2(unsigned long long v) {
    unsigned int lo, hi;
    asm("mov.b64 {%0, %1}, %2;" : "=r"(lo), "=r"(hi) : "l"(v));
    return make_float2(__uint_as_float(lo), __uint_as_float(hi));
}

__global__ void __launch_bounds__(THREADS, 1)
ca_fused_kernel(const float* __restrict__ x,
                const float* __restrict__ y,
                const float* __restrict__ ln_g,
                const float* __restrict__ ln_b,
                const float* __restrict__ Wq,
                const float* __restrict__ Wkv,
                const float* __restrict__ Wo,
                const float* __restrict__ bo,
                float* __restrict__ out,
                int P)
{
    extern __shared__ float sm[];
    float* sWq  = sm + OFF_WQ;
    float* sWkv = sm + OFF_WKV;
    float* sKV  = sm + OFF_KV;
    float* sYT  = sm + OFF_YT;
    float* sXN  = sm + OFF_XN;
    float* sXO  = sm + OFF_XO;
    float* sQ   = sm + OFF_Q;
    float* sAO  = sm + OFF_AO;
    float* sAT  = sm + OFF_AT;
    float* sBUF = sm + OFF_BUF;
    float* sBO  = sm + OFF_BO;
    float* sG   = sm + OFF_G;
    float* sB   = sm + OFF_B;

    const int tid  = threadIdx.x;
    const int warp = tid >> 5;
    const int lane = tid & 31;
    const int rg   = tid >> 6;   // 0..3 : row group (4 rows of kv)
    const int cg   = tid & 63;   // 0..63: col group (4 cols of kv)
    const int jj   = tid & 127;  // output column for Wo GEMM
    const int hf   = tid >> 7;   // 0/1  : i-half for Wo GEMM

    // ---- load weights into SMEM (once) ----
    {
        const float4* s4 = (const float4*)Wq;
        float4* d4 = (float4*)sWq;
        for (int u = tid; u < 4096; u += THREADS) d4[u] = s4[u];
        const float4* s42 = (const float4*)Wkv;
        float4* d42 = (float4*)sWkv;
        for (int u = tid; u < 8192; u += THREADS) d42[u] = s42[u];
        if (tid < 128) { sBO[tid] = bo[tid]; sG[tid] = ln_g[tid]; sB[tid] = ln_b[tid]; }
    }
    // ---- Wo into registers: thread holds Wo[hf*64 + ii][jj], ii=0..63 ----
    float wo[64];
#pragma unroll
    for (int ii = 0; ii < 64; ++ii) wo[ii] = Wo[(hf * 64 + ii) * 128 + jj];

    __syncthreads();

    for (int pt = blockIdx.x; pt < P; pt += gridDim.x) {
        // ---- stage raw y (16x128) + x (128) into sKV region (coalesced f4) ----
        {
            const float4* y4 = (const float4*)y + (size_t)pt * 512;
            const float4* x4 = (const float4*)x + (size_t)pt * 32;
            float4* raw = (float4*)sKV;
            for (int u = tid; u < 544; u += THREADS)
                raw[u] = (u < 512) ? y4[u] : x4[u - 512];
        }
        __syncthreads();

        // ---- LayerNorm: 17 rows (16 y rows -> sYT transposed, row 16 = x -> sXN) ----
        for (int r = warp; r < 17; r += 8) {
            const float* row = sKV + r * 128;
            float v0 = row[lane], v1 = row[lane + 32], v2 = row[lane + 64], v3 = row[lane + 96];
            float s  = v0 + v1 + v2 + v3;
            float q2 = v0 * v0 + v1 * v1 + v2 * v2 + v3 * v3;
#pragma unroll
            for (int o = 16; o > 0; o >>= 1) {
                s  += __shfl_xor_sync(0xffffffffu, s,  o);
                q2 += __shfl_xor_sync(0xffffffffu, q2, o);
            }
            float mu  = s * (1.0f / 128.0f);
            float var = q2 * (1.0f / 128.0f) - mu * mu;
            float rs  = rsqrtf(var + 1e-5f);
            float vs[4] = {v0, v1, v2, v3};
            if (r < 16) {
#pragma unroll
                for (int k = 0; k < 4; ++k) {
                    int i = lane + k * 32;
                    sYT[i * YSTR + r] = (vs[k] - mu) * rs * sG[i] + sB[i];
                }
            } else {
#pragma unroll
                for (int k = 0; k < 4; ++k) {
                    int i = lane + k * 32;
                    sXN[i] = (vs[k] - mu) * rs * sG[i] + sB[i];
                    sXO[i] = vs[k];
                }
            }
        }
        __syncthreads();

        // ---- kv GEMM: yn[16,128] @ Wkv[128,256] -> sKV[16,256]  (packed f32x2) ----
        unsigned long long a00 = 0, a01 = 0, a10 = 0, a11 = 0;
        unsigned long long a20 = 0, a21 = 0, a30 = 0, a31 = 0;
        {
            const float* yt = sYT + rg * 4;
            const float* wk = sWkv + cg * 4;
#pragma unroll 4
            for (int i = 0; i < 128; ++i) {
                float4 yv = *(const float4*)(yt + i * YSTR);         // 4 rows, broadcast
                ulonglong2 wv = *(const ulonglong2*)(wk + i * 256);  // 4 cols as 2x f32x2
                unsigned long long p;
                p = pk2(yv.x); ffma2(a00, p, wv.x); ffma2(a01, p, wv.y);
                p = pk2(yv.y); ffma2(a10, p, wv.x); ffma2(a11, p, wv.y);
                p = pk2(yv.z); ffma2(a20, p, wv.x); ffma2(a21, p, wv.y);
                p = pk2(yv.w); ffma2(a30, p, wv.x); ffma2(a31, p, wv.y);
            }
        }
        {
            float* dst = sKV + (rg * 4) * 256 + cg * 4;
            float2 lo, hi;
            lo = upk2(a00); hi = upk2(a01); *(float4*)(dst)        = make_float4(lo.x, lo.y, hi.x, hi.y);
            lo = upk2(a10); hi = upk2(a11); *(float4*)(dst + 256)  = make_float4(lo.x, lo.y, hi.x, hi.y);
            lo = upk2(a20); hi = upk2(a21); *(float4*)(dst + 512)  = make_float4(lo.x, lo.y, hi.x, hi.y);
            lo = upk2(a30); hi = upk2(a31); *(float4*)(dst + 768)  = make_float4(lo.x, lo.y, hi.x, hi.y);
        }

        // ---- q GEMM: xn[128] @ Wq[128,128] ----
        if (tid < 128) {
            float a = 0.0f;
#pragma unroll 8
            for (int i = 0; i < 128; ++i) a = fmaf(sXN[i], sWq[i * 128 + tid], a);
            sQ[tid] = a;
        }
        __syncthreads();

        // ---- dots + softmax over m=16, per head (threads 0..63) ----
        if (tid < 64) {
            int h = tid >> 4, m = tid & 15;
            const float* kk = sKV + m * 256 + h * 32;  // k = cols [0,128)
            const float* qq = sQ + h * 32;
            float dsum = 0.0f;
#pragma unroll
            for (int dd = 0; dd < 8; ++dd) {
                float4 k4 = *(const float4*)(kk + dd * 4);
                float4 q4 = *(const float4*)(qq + dd * 4);
                dsum += k4.x * q4.x + k4.y * q4.y + k4.z * q4.z + k4.w * q4.w;
            }
            dsum *= 0.17677669529663687f;  // 32^-0.5
            float mx = dsum;
#pragma unroll
            for (int o = 8; o > 0; o >>= 1)
                mx = fmaxf(mx, __shfl_xor_sync(0xffffffffu, mx, o));
            float e = __expf(dsum - mx);
            float se = e;
#pragma unroll
            for (int o = 8; o > 0; o >>= 1)
                se += __shfl_xor_sync(0xffffffffu, se, o);
            sAT[tid] = e / se;
        }
        __syncthreads();

        // ---- attention output: ao[h,d] = sum_m attn[h,m] * v[m,h,d] ----
        if (tid < 128) {
            int h = tid >> 5, d = tid & 31;
            const float* vv = sKV + 128 + h * 32 + d;  // v = cols [128,256)
            const float* at = sAT + h * 16;
            float a = 0.0f;
#pragma unroll
            for (int m = 0; m < 16; ++m) a = fmaf(at[m], vv[m * 256], a);
            sAO[tid] = a;
        }
        __syncthreads();

        // ---- out GEMM: ao[128] @ Wo[128,128] + bo + x  (Wo in registers) ----
        {
            const float* ain = sAO + hf * 64;
            float p = 0.0f;
#pragma unroll
            for (int ii = 0; ii < 64; ++ii) p = fmaf(ain[ii], wo[ii], p);
            if (hf) sBUF[jj] = p;
            __syncthreads();
            if (!hf) out[(size_t)pt * 128 + jj] = p + sBUF[jj] + sBO[jj] + sXO[jj];
        }
        __syncthreads();  // protect sKV/sBUF before next point's staging
    }
}

extern "C" void kernel_launch(void* const* d_in, const int* in_sizes, int n_in,
                              void* d_out, int out_size) {
    const float* x    = (const float*)d_in[0];
    const float* y    = (const float*)d_in[1];
    const float* ln_g = (const float*)d_in[2];
    const float* ln_b = (const float*)d_in[3];
    const float* Wq   = (const float*)d_in[4];
    const float* Wkv  = (const float*)d_in[5];
    const float* Wo   = (const float*)d_in[6];
    const float* bo   = (const float*)d_in[7];
    float* out = (float*)d_out;

    const int P = in_sizes[0] / 128;  // total (b*n) points

    int dev = 0;
    cudaGetDevice(&dev);
    int sms = 0;
    cudaDeviceGetAttribute(&sms, cudaDevAttrMultiProcessorCount, dev);
    if (sms <= 0) sms = 148;

    const size_t smem_bytes = (size_t)SMEM_FLOATS * sizeof(float);  // 227584
    cudaFuncSetAttribute(ca_fused_kernel,
                         cudaFuncAttributeMaxDynamicSharedMemorySize,
                         (int)smem_bytes);

    ca_fused_kernel<<<sms, THREADS, smem_bytes>>>(
        x, y, ln_g, ln_b, Wq, Wkv, Wo, bo, out, P);
}

// round 12
// speedup vs baseline: 2.4523x; 2.4425x over previous
#include <cuda_runtime.h>
#include <cuda_bf16.h>

// Fused PreNorm cross-attention using warp-level tensor cores (mma.sync bf16,
// fp32 accumulate) -- tcgen05 is unavailable (harness compiles at sm_103).
//
// Per CTA iteration ("chunk"): 8 points.
//   kv GEMM: D[128m x 256n] = yn[128x128] @ Wkv[128x256], bf16x3 split
//   (AhBh + AlBh + AhBl), 8 warps each owning a 64m x 64n tile in registers.
//   Epilogue computes dots and attn*v directly from MMA fragments.
//   q GEMM / out GEMM on CUDA cores (FFMA2) with weights streamed from L2.

#define THREADS 256
#define SCALE_F 0.17677669529663687f

typedef unsigned long long ull;

// ---- smem byte offsets ----
#define OFF_BHI 0        // 65536 : Wkv hi bf16 [n=256][k=128], xor-swizzled
#define OFF_BLO 65536    // 65536 : Wkv lo
#define OFF_AHI 131072   // 32768 : yn hi [m=128][k=128], xor-swizzled
#define OFF_ALO 163840   // 32768 : yn lo
#define OFF_XNT 196608   // 4096  : xn transposed [i=128][p=8] fp32
#define OFF_XOR 200704   // 4096  : raw x [p=8][128]
#define OFF_Q   204800   // 4096  : q [p=8][128]
#define OFF_DOT 208896   // 2048  : dots/attn [(p*4+h)=32][m=16]
#define OFF_TMP 210944   // 4096  : half-combine temp [p=8][128]
#define OFF_AOT 215040   // 4096  : attn-out transposed [i=128][p=8]
#define OFF_G   219136   // 512
#define OFF_B   219648   // 512
#define OFF_BOV 220160   // 512
#define SMEM_BYTES 220672

// xor-swizzled tile offset: row stride 256B (128 bf16), 16B chunks xor'd by row&7
static __device__ __forceinline__ int sw_off(int row, int k) {
    return row * 256 + ((((k >> 3) ^ (row & 7)) << 4)) + ((k & 7) << 1);
}

static __device__ __forceinline__ unsigned smem_u32(const void* p) {
    unsigned a;
    asm("{ .reg .u64 t; cvta.to.shared.u64 t, %1; cvt.u32.u64 %0, t; }"
        : "=r"(a) : "l"(p));
    return a;
}
static __device__ __forceinline__ ull pk2(float v) {
    ull r;
    unsigned b = __float_as_uint(v);
    asm("mov.b64 %0, {%1, %1};" : "=l"(r) : "r"(b));
    return r;
}
static __device__ __forceinline__ void ffma2(ull& a, ull x, ull w) {
    asm("fma.rn.f32x2 %0, %1, %2, %0;" : "+l"(a) : "l"(x), "l"(w));
}
static __device__ __forceinline__ float2 upk2(ull v) {
    unsigned lo, hi;
    asm("mov.b64 {%0, %1}, %2;" : "=r"(lo), "=r"(hi) : "l"(v));
    return make_float2(__uint_as_float(lo), __uint_as_float(hi));
}
static __device__ __forceinline__ void bsplit(float v, unsigned short& h,
                                              unsigned short& l) {
    __nv_bfloat16 bh = __float2bfloat16(v);
    float hv = __bfloat162float(bh);
    __nv_bfloat16 bl = __float2bfloat16(v - hv);
    h = __bfloat16_as_ushort(bh);
    l = __bfloat16_as_ushort(bl);
}
static __device__ __forceinline__ void ldsm4(unsigned* r, unsigned addr) {
    asm volatile("ldmatrix.sync.aligned.m8n8.x4.shared.b16 {%0,%1,%2,%3}, [%4];"
                 : "=r"(r[0]), "=r"(r[1]), "=r"(r[2]), "=r"(r[3]) : "r"(addr));
}
static __device__ __forceinline__ void mma16816(float* d, const unsigned* a,
                                                const unsigned* b) {
    asm volatile(
        "mma.sync.aligned.m16n8k16.row.col.f32.bf16.bf16.f32 "
        "{%0,%1,%2,%3}, {%4,%5,%6,%7}, {%8,%9}, {%0,%1,%2,%3};"
        : "+f"(d[0]), "+f"(d[1]), "+f"(d[2]), "+f"(d[3])
        : "r"(a[0]), "r"(a[1]), "r"(a[2]), "r"(a[3]), "r"(b[0]), "r"(b[1]));
}

__global__ void __launch_bounds__(THREADS, 1)
ca_mma_kernel(const float* __restrict__ x,
              const float* __restrict__ y,
              const float* __restrict__ ln_g,
              const float* __restrict__ ln_b,
              const float* __restrict__ Wq,
              const float* __restrict__ Wkv,
              const float* __restrict__ Wo,
              const float* __restrict__ bo,
              float* __restrict__ out,
              int P)
{
    extern __shared__ float smf[];
    char* smb = (char*)smf;
    const unsigned sb = smem_u32(smf);

    const int tid  = threadIdx.x;
    const int warp = tid >> 5;
    const int lane = tid & 31;
    const int gid  = lane >> 2;   // 0..7
    const int tig  = lane & 3;    // 0..3
    const int jj   = tid & 127;
    const int hf   = tid >> 7;

    float* sXNT = (float*)(smb + OFF_XNT);
    float* sXOR = (float*)(smb + OFF_XOR);
    float* sQ   = (float*)(smb + OFF_Q);
    float* sDOT = (float*)(smb + OFF_DOT);
    float* sTMP = (float*)(smb + OFF_TMP);
    float* sAOT = (float*)(smb + OFF_AOT);
    float* sG   = (float*)(smb + OFF_G);
    float* sB   = (float*)(smb + OFF_B);
    float* sBO  = (float*)(smb + OFF_BOV);

    if (tid < 128) { sG[tid] = ln_g[tid]; sB[tid] = ln_b[tid]; sBO[tid] = bo[tid]; }

    // ---- Wkv -> bf16 hi/lo swizzled B tiles [n][k] (once per CTA) ----
    for (int idx = tid; idx < 32768; idx += THREADS) {
        int k = idx >> 8, n = idx & 255;      // Wkv[k][n], coalesced read
        unsigned short h, l;
        bsplit(Wkv[idx], h, l);
        int o = sw_off(n, k);
        *(unsigned short*)(smb + OFF_BHI + o) = h;
        *(unsigned short*)(smb + OFF_BLO + o) = l;
    }
    __syncthreads();

    // warp tiling: 2 m-halves x 4 n-columns
    const int mrow0 = (warp >> 2) * 64;       // 0 / 64
    const int ncol0 = (warp & 3) * 64;        // 0..192
    const bool is_k = ((warp & 3) < 2);       // n < 128 -> k part
    const int pbase = (warp >> 2) * 4;

    // per-lane ldmatrix addressing (invariant parts)
    const int rowA  = mrow0 + (lane & 15);
    const int kca   = lane >> 4;
    const int swa   = rowA & 7;
    const int nrowB = ncol0 + (lane & 7) + ((lane >> 4) & 1) * 8;
    const int kcb   = (lane >> 3) & 1;
    const int swb   = nrowB & 7;

    const unsigned abase[3] = {OFF_AHI, OFF_ALO, OFF_AHI};
    const unsigned bbase[3] = {OFF_BHI, OFF_BHI, OFF_BLO};

    const int nch = P >> 3;
    for (int c = blockIdx.x; c < nch; c += gridDim.x) {
        const long long pt0 = (long long)c * 8;

        // ============ LN + pack: 128 y rows -> A hi/lo, 8 x rows -> XNT ======
        for (int r = warp; r < 136; r += 8) {
            float4 v4;
            if (r < 128) v4 = ((const float4*)y)[(pt0 * 16 + r) * 32 + lane];
            else         v4 = ((const float4*)x)[(pt0 + (r - 128)) * 32 + lane];
            float s  = v4.x + v4.y + v4.z + v4.w;
            float q2 = v4.x * v4.x + v4.y * v4.y + v4.z * v4.z + v4.w * v4.w;
#pragma unroll
            for (int o = 16; o > 0; o >>= 1) {
                s  += __shfl_xor_sync(0xffffffffu, s,  o);
                q2 += __shfl_xor_sync(0xffffffffu, q2, o);
            }
            float mu  = s * (1.0f / 128.0f);
            float var = q2 * (1.0f / 128.0f) - mu * mu;
            float rs  = rsqrtf(var + 1e-5f);
            int k0 = lane * 4;
            float n0 = (v4.x - mu) * rs * sG[k0]     + sB[k0];
            float n1 = (v4.y - mu) * rs * sG[k0 + 1] + sB[k0 + 1];
            float n2 = (v4.z - mu) * rs * sG[k0 + 2] + sB[k0 + 2];
            float n3 = (v4.w - mu) * rs * sG[k0 + 3] + sB[k0 + 3];
            if (r < 128) {
                unsigned short h0, l0, h1, l1, h2, l2, h3, l3;
                bsplit(n0, h0, l0); bsplit(n1, h1, l1);
                bsplit(n2, h2, l2); bsplit(n3, h3, l3);
                int boff = r * 256 + ((((k0 >> 3) ^ (r & 7)) << 4)) + ((k0 & 7) << 1);
                *(uint2*)(smb + OFF_AHI + boff) =
                    make_uint2((unsigned)h0 | ((unsigned)h1 << 16),
                               (unsigned)h2 | ((unsigned)h3 << 16));
                *(uint2*)(smb + OFF_ALO + boff) =
                    make_uint2((unsigned)l0 | ((unsigned)l1 << 16),
                               (unsigned)l2 | ((unsigned)l3 << 16));
            } else {
                int p = r - 128;
                sXNT[(k0)     * 8 + p] = n0;
                sXNT[(k0 + 1) * 8 + p] = n1;
                sXNT[(k0 + 2) * 8 + p] = n2;
                sXNT[(k0 + 3) * 8 + p] = n3;
                *(float4*)(sXOR + p * 128 + k0) = v4;
            }
        }
        __syncthreads();

        // ============ q GEMM on cores (Wq from L2, xn from SMEM) ============
        {
            ull qa0 = 0, qa1 = 0, qa2 = 0, qa3 = 0;
            const float* xt  = sXNT + hf * 64 * 8;
            const float* wqp = Wq + (hf * 64) * 128 + jj;
#pragma unroll 8
            for (int ii = 0; ii < 64; ++ii) {
                ulonglong2 xa = *(const ulonglong2*)(xt + ii * 8);
                ulonglong2 xb = *(const ulonglong2*)(xt + ii * 8 + 4);
                ull w = pk2(wqp[ii * 128]);
                ffma2(qa0, xa.x, w); ffma2(qa1, xa.y, w);
                ffma2(qa2, xb.x, w); ffma2(qa3, xb.y, w);
            }
            float2 f0 = upk2(qa0), f1 = upk2(qa1), f2 = upk2(qa2), f3 = upk2(qa3);
            if (hf) {
                sTMP[0 * 128 + jj] = f0.x; sTMP[1 * 128 + jj] = f0.y;
                sTMP[2 * 128 + jj] = f1.x; sTMP[3 * 128 + jj] = f1.y;
                sTMP[4 * 128 + jj] = f2.x; sTMP[5 * 128 + jj] = f2.y;
                sTMP[6 * 128 + jj] = f3.x; sTMP[7 * 128 + jj] = f3.y;
            }
            __syncthreads();
            if (!hf) {
                sQ[0 * 128 + jj] = f0.x + sTMP[0 * 128 + jj];
                sQ[1 * 128 + jj] = f0.y + sTMP[1 * 128 + jj];
                sQ[2 * 128 + jj] = f1.x + sTMP[2 * 128 + jj];
                sQ[3 * 128 + jj] = f1.y + sTMP[3 * 128 + jj];
                sQ[4 * 128 + jj] = f2.x + sTMP[4 * 128 + jj];
                sQ[5 * 128 + jj] = f2.y + sTMP[5 * 128 + jj];
                sQ[6 * 128 + jj] = f3.x + sTMP[6 * 128 + jj];
                sQ[7 * 128 + jj] = f3.y + sTMP[7 * 128 + jj];
            }
            __syncthreads();
        }

        // ============ kv GEMM: warp tile 64m x 64n, 3 bf16 terms ============
        float acc[4][8][4];
#pragma unroll
        for (int mt = 0; mt < 4; ++mt)
#pragma unroll
            for (int nt = 0; nt < 8; ++nt)
#pragma unroll
                for (int e = 0; e < 4; ++e) acc[mt][nt][e] = 0.0f;

#pragma unroll 1
        for (int t = 0; t < 3; ++t) {
            const unsigned sa  = sb + abase[t] + (unsigned)(rowA * 256);
            const unsigned sbb = sb + bbase[t] + (unsigned)(nrowB * 256);
#pragma unroll
            for (int ks = 0; ks < 8; ++ks) {
                unsigned bfr[4][4];
                unsigned bko = (unsigned)((((ks * 2 + kcb) ^ swb)) << 4);
#pragma unroll
                for (int np = 0; np < 4; ++np)
                    ldsm4(bfr[np], sbb + np * 4096 + bko);
                unsigned ako = (unsigned)((((ks * 2 + kca) ^ swa)) << 4);
#pragma unroll
                for (int mt = 0; mt < 4; ++mt) {
                    unsigned af[4];
                    ldsm4(af, sa + mt * 4096 + ako);
#pragma unroll
                    for (int np = 0; np < 4; ++np) {
                        mma16816(acc[mt][np * 2],     af, &bfr[np][0]);
                        mma16816(acc[mt][np * 2 + 1], af, &bfr[np][2]);
                    }
                }
            }
        }

        // ============ dots from k-fragments (warps 0,1,4,5) ============
        if (is_k) {
            const int hb = (warp & 3) * 2;
#pragma unroll
            for (int mt = 0; mt < 4; ++mt) {
                int p = pbase + mt;
                float d0a = 0, d1a = 0, d0b = 0, d1b = 0;
#pragma unroll
                for (int nt = 0; nt < 8; ++nt) {
                    int h  = hb + (nt >> 2);
                    int dl = (nt & 3) * 8 + tig * 2;
                    float2 qv = *(const float2*)(sQ + p * 128 + h * 32 + dl);
                    const float* cc = acc[mt][nt];
                    if (nt < 4) {
                        d0a += cc[0] * qv.x + cc[1] * qv.y;
                        d1a += cc[2] * qv.x + cc[3] * qv.y;
                    } else {
                        d0b += cc[0] * qv.x + cc[1] * qv.y;
                        d1b += cc[2] * qv.x + cc[3] * qv.y;
                    }
                }
#pragma unroll
                for (int o = 1; o < 4; o <<= 1) {
                    d0a += __shfl_xor_sync(0xffffffffu, d0a, o);
                    d1a += __shfl_xor_sync(0xffffffffu, d1a, o);
                    d0b += __shfl_xor_sync(0xffffffffu, d0b, o);
                    d1b += __shfl_xor_sync(0xffffffffu, d1b, o);
                }
                if (tig == 0) {
                    sDOT[(p * 4 + hb) * 16 + gid]         = d0a * SCALE_F;
                    sDOT[(p * 4 + hb) * 16 + gid + 8]     = d1a * SCALE_F;
                    sDOT[(p * 4 + hb + 1) * 16 + gid]     = d0b * SCALE_F;
                    sDOT[(p * 4 + hb + 1) * 16 + gid + 8] = d1b * SCALE_F;
                }
            }
        }
        __syncthreads();

        // ============ softmax over m=16 (32 rows) ============
        if (tid < 32) {
            float* dd = sDOT + tid * 16;
            float mx = dd[0];
#pragma unroll
            for (int m = 1; m < 16; ++m) mx = fmaxf(mx, dd[m]);
            float se = 0.0f;
            float ee[16];
#pragma unroll
            for (int m = 0; m < 16; ++m) { ee[m] = __expf(dd[m] - mx); se += ee[m]; }
            float inv = 1.0f / se;
#pragma unroll
            for (int m = 0; m < 16; ++m) dd[m] = ee[m] * inv;
        }
        __syncthreads();

        // ============ attn * v from v-fragments (warps 2,3,6,7) ============
        if (!is_k) {
            const int hb = ((warp & 3) - 2) * 2;
#pragma unroll
            for (int mt = 0; mt < 4; ++mt) {
                int p = pbase + mt;
                float aAg  = sDOT[(p * 4 + hb) * 16 + gid];
                float aAg8 = sDOT[(p * 4 + hb) * 16 + gid + 8];
                float aBg  = sDOT[(p * 4 + hb + 1) * 16 + gid];
                float aBg8 = sDOT[(p * 4 + hb + 1) * 16 + gid + 8];
#pragma unroll
                for (int nt = 0; nt < 8; ++nt) {
                    float ag  = (nt < 4) ? aAg  : aBg;
                    float ag8 = (nt < 4) ? aAg8 : aBg8;
                    const float* cc = acc[mt][nt];
                    float o0 = ag * cc[0] + ag8 * cc[2];
                    float o1 = ag * cc[1] + ag8 * cc[3];
#pragma unroll
                    for (int o = 4; o < 32; o <<= 1) {
                        o0 += __shfl_xor_sync(0xffffffffu, o0, o);
                        o1 += __shfl_xor_sync(0xffffffffu, o1, o);
                    }
                    if (gid == 0) {
                        int h  = hb + (nt >> 2);
                        int d0 = (nt & 3) * 8 + tig * 2;
                        sAOT[(h * 32 + d0) * 8 + p]     = o0;
                        sAOT[(h * 32 + d0 + 1) * 8 + p] = o1;
                    }
                }
            }
        }
        __syncthreads();

        // ============ out GEMM (Wo from L2) + bias + residual ============
        {
            ull oa0 = 0, oa1 = 0, oa2 = 0, oa3 = 0;
            const float* at  = sAOT + hf * 64 * 8;
            const float* wop = Wo + (hf * 64) * 128 + jj;
#pragma unroll 8
            for (int ii = 0; ii < 64; ++ii) {
                ulonglong2 xa = *(const ulonglong2*)(at + ii * 8);
                ulonglong2 xb = *(const ulonglong2*)(at + ii * 8 + 4);
                ull w = pk2(wop[ii * 128]);
                ffma2(oa0, xa.x, w); ffma2(oa1, xa.y, w);
                ffma2(oa2, xb.x, w); ffma2(oa3, xb.y, w);
            }
            float2 f0 = upk2(oa0), f1 = upk2(oa1), f2 = upk2(oa2), f3 = upk2(oa3);
            if (hf) {
                sTMP[0 * 128 + jj] = f0.x; sTMP[1 * 128 + jj] = f0.y;
                sTMP[2 * 128 + jj] = f1.x; sTMP[3 * 128 + jj] = f1.y;
                sTMP[4 * 128 + jj] = f2.x; sTMP[5 * 128 + jj] = f2.y;
                sTMP[6 * 128 + jj] = f3.x; sTMP[7 * 128 + jj] = f3.y;
            }
            __syncthreads();
            if (!hf) {
                float rr[8] = { f0.x, f0.y, f1.x, f1.y, f2.x, f2.y, f3.x, f3.y };
#pragma unroll
                for (int p = 0; p < 8; ++p) {
                    float v = rr[p] + sTMP[p * 128 + jj] + sBO[jj] + sXOR[p * 128 + jj];
                    out[(pt0 + p) * 128 + jj] = v;
                }
            }
            __syncthreads();   // protect sTMP/sQ/sDOT/A tiles before next chunk
        }
    }
}

extern "C" void kernel_launch(void* const* d_in, const int* in_sizes, int n_in,
                              void* d_out, int out_size) {
    const float* x    = (const float*)d_in[0];
    const float* y    = (const float*)d_in[1];
    const float* ln_g = (const float*)d_in[2];
    const float* ln_b = (const float*)d_in[3];
    const float* Wq   = (const float*)d_in[4];
    const float* Wkv  = (const float*)d_in[5];
    const float* Wo   = (const float*)d_in[6];
    const float* bo   = (const float*)d_in[7];
    float* out = (float*)d_out;

    const int P = in_sizes[0] / 128;   // (b*n) points

    int dev = 0;
    cudaGetDevice(&dev);
    int sms = 0;
    cudaDeviceGetAttribute(&sms, cudaDevAttrMultiProcessorCount, dev);
    if (sms <= 0) sms = 148;

    cudaFuncSetAttribute(ca_mma_kernel,
                         cudaFuncAttributeMaxDynamicSharedMemorySize, SMEM_BYTES);

    ca_mma_kernel<<<sms, THREADS, SMEM_BYTES>>>(
        x, y, ln_g, ln_b, Wq, Wkv, Wo, bo, out, P);
}

// round 13
// speedup vs baseline: 3.8238x; 1.5593x over previous
#include <cuda_runtime.h>
#include <cuda_fp16.h>

// Fused PreNorm cross-attention, warp-level HMMA (mma.sync m16n8k16 fp16,
// fp32 accumulate). 512 threads / 16 warps per CTA, 1 CTA/SM persistent.
//
// Per chunk: 8 points. kv GEMM D[128m x 256n] = yn @ Wkv via fp16 2-term
// split: A = Ah + Al (exact), B = fp16(Wkv); D = Ah*Bh + Al*Bh.
// Each warp owns a 64m x 32n tile (acc in 64 regs). Epilogue (dots, attn*v)
// computed directly from MMA fragments. q/out GEMMs on CUDA cores with
// 4-way contraction split across thread quarters, weights streamed from L2.

#define THREADS 512
#define SCALE_F 0.17677669529663687f
typedef unsigned long long ull;

// ---- smem byte offsets ----
#define OFF_BH  0        // 65536 : Wkv fp16 [n=256][k=128], xor-swizzled
#define OFF_AH  65536    // 32768 : yn hi fp16 [m=128][k=128], xor-swizzled
#define OFF_AL  98304    // 32768 : yn lo fp16
#define OFF_XNT 131072   // 4096  : xn transposed [i=128][p=8] fp32
#define OFF_Q   135168   // 4096  : q [p=8][128]
#define OFF_DOT 139264   // 2048  : dots/attn [(p*4+h)=32][m=16]
#define OFF_TMP 141312   // 12288 : 3 partial buffers [8][128] fp32
#define OFF_AOT 153600   // 4096  : attn-out transposed [i=128][p=8]
#define OFF_G   157696   // 512
#define OFF_B   158208   // 512
#define OFF_BOV 158720   // 512
#define SMEM_BYTES 159232

// xor-swizzled tile offset: row stride 256B (128 fp16), 16B chunks xor'd by row&7
static __device__ __forceinline__ int sw_off(int row, int k) {
    return row * 256 + ((((k >> 3) ^ (row & 7)) << 4)) + ((k & 7) << 1);
}
static __device__ __forceinline__ unsigned smem_u32(const void* p) {
    unsigned a;
    asm("{ .reg .u64 t; cvta.to.shared.u64 t, %1; cvt.u32.u64 %0, t; }"
        : "=r"(a) : "l"(p));
    return a;
}
static __device__ __forceinline__ ull pk2(float v) {
    ull r;
    unsigned b = __float_as_uint(v);
    asm("mov.b64 %0, {%1, %1};" : "=l"(r) : "r"(b));
    return r;
}
static __device__ __forceinline__ void ffma2(ull& a, ull x, ull w) {
    asm("fma.rn.f32x2 %0, %1, %2, %0;" : "+l"(a) : "l"(x), "l"(w));
}
static __device__ __forceinline__ float2 upk2(ull v) {
    unsigned lo, hi;
    asm("mov.b64 {%0, %1}, %2;" : "=r"(lo), "=r"(hi) : "l"(v));
    return make_float2(__uint_as_float(lo), __uint_as_float(hi));
}
// fp16 hi/lo split (A exact to 2^-22)
static __device__ __forceinline__ void hsplit(float v, unsigned short& h,
                                              unsigned short& l) {
    __half hh = __float2half_rn(v);
    float hv = __half2float(hh);
    __half ll = __float2half_rn(v - hv);
    h = __half_as_ushort(hh);
    l = __half_as_ushort(ll);
}
static __device__ __forceinline__ void ldsm4(unsigned* r, unsigned addr) {
    asm volatile("ldmatrix.sync.aligned.m8n8.x4.shared.b16 {%0,%1,%2,%3}, [%4];"
                 : "=r"(r[0]), "=r"(r[1]), "=r"(r[2]), "=r"(r[3]) : "r"(addr));
}
static __device__ __forceinline__ void mma16816(float* d, const unsigned* a,
                                                const unsigned* b) {
    asm volatile(
        "mma.sync.aligned.m16n8k16.row.col.f32.f16.f16.f32 "
        "{%0,%1,%2,%3}, {%4,%5,%6,%7}, {%8,%9}, {%0,%1,%2,%3};"
        : "+f"(d[0]), "+f"(d[1]), "+f"(d[2]), "+f"(d[3])
        : "r"(a[0]), "r"(a[1]), "r"(a[2]), "r"(a[3]), "r"(b[0]), "r"(b[1]));
}

__global__ void __launch_bounds__(THREADS, 1)
ca_mma512_kernel(const float* __restrict__ x,
                 const float* __restrict__ y,
                 const float* __restrict__ ln_g,
                 const float* __restrict__ ln_b,
                 const float* __restrict__ Wq,
                 const float* __restrict__ Wkv,
                 const float* __restrict__ Wo,
                 const float* __restrict__ bo,
                 float* __restrict__ out,
                 int P)
{
    extern __shared__ float smf[];
    char* smb = (char*)smf;
    const unsigned sb = smem_u32(smf);

    const int tid  = threadIdx.x;
    const int warp = tid >> 5;
    const int lane = tid & 31;
    const int gid  = lane >> 2;     // 0..7
    const int tig  = lane & 3;      // 0..3
    const int jj   = tid & 127;
    const int qq   = tid >> 7;      // 0..3 : contraction quarter

    float* sXNT = (float*)(smb + OFF_XNT);
    float* sQ   = (float*)(smb + OFF_Q);
    float* sDOT = (float*)(smb + OFF_DOT);
    float* sTMP = (float*)(smb + OFF_TMP);
    float* sAOT = (float*)(smb + OFF_AOT);
    float* sG   = (float*)(smb + OFF_G);
    float* sB   = (float*)(smb + OFF_B);
    float* sBO  = (float*)(smb + OFF_BOV);

    if (tid < 128) { sG[tid] = ln_g[tid]; sB[tid] = ln_b[tid]; sBO[tid] = bo[tid]; }

    // ---- Wkv -> fp16 swizzled B tile [n][k] (once per CTA) ----
    for (int idx = tid; idx < 32768; idx += THREADS) {
        int k = idx >> 8, n = idx & 255;   // Wkv[k][n], coalesced read
        *(unsigned short*)(smb + OFF_BH + sw_off(n, k)) =
            __half_as_ushort(__float2half_rn(Wkv[idx]));
    }
    __syncthreads();

    // warp tiling: 2 m-halves x 8 n-tiles of 32
    const int mh    = warp >> 3;          // 0/1
    const int nn    = warp & 7;           // 0..7
    const bool is_k = (nn < 4);
    const int head  = is_k ? nn : (nn - 4);
    const int pbase = mh * 4;

    // ldmatrix per-lane addressing (loop-invariant parts)
    const int rowA  = mh * 64 + (lane & 15);
    const int kca   = lane >> 4;
    const int swa   = rowA & 7;
    const int nrowB = nn * 32 + (lane & 7) + ((lane >> 4) & 1) * 8;
    const int kcb   = (lane >> 3) & 1;
    const int swb   = nrowB & 7;
    const unsigned sbb = sb + OFF_BH + (unsigned)(nrowB * 256);
    const unsigned saH = sb + OFF_AH + (unsigned)(rowA * 256);
    const unsigned saL = sb + OFF_AL + (unsigned)(rowA * 256);

    const int nch = P >> 3;
    for (int c = blockIdx.x; c < nch; c += gridDim.x) {
        const long long pt0 = (long long)c * 8;

        // ============ LN + pack: 128 y rows -> A hi/lo, 8 x rows -> XNT ======
        for (int r = warp; r < 136; r += 16) {
            float4 v4;
            if (r < 128) v4 = ((const float4*)y)[(pt0 * 16 + r) * 32 + lane];
            else         v4 = ((const float4*)x)[(pt0 + (r - 128)) * 32 + lane];
            float s  = v4.x + v4.y + v4.z + v4.w;
            float q2 = v4.x * v4.x + v4.y * v4.y + v4.z * v4.z + v4.w * v4.w;
#pragma unroll
            for (int o = 16; o > 0; o >>= 1) {
                s  += __shfl_xor_sync(0xffffffffu, s,  o);
                q2 += __shfl_xor_sync(0xffffffffu, q2, o);
            }
            float mu  = s * (1.0f / 128.0f);
            float var = q2 * (1.0f / 128.0f) - mu * mu;
            float rs  = rsqrtf(var + 1e-5f);
            int k0 = lane * 4;
            float n0 = (v4.x - mu) * rs * sG[k0]     + sB[k0];
            float n1 = (v4.y - mu) * rs * sG[k0 + 1] + sB[k0 + 1];
            float n2 = (v4.z - mu) * rs * sG[k0 + 2] + sB[k0 + 2];
            float n3 = (v4.w - mu) * rs * sG[k0 + 3] + sB[k0 + 3];
            if (r < 128) {
                unsigned short h0, l0, h1, l1, h2, l2, h3, l3;
                hsplit(n0, h0, l0); hsplit(n1, h1, l1);
                hsplit(n2, h2, l2); hsplit(n3, h3, l3);
                int boff = r * 256 + ((((k0 >> 3) ^ (r & 7)) << 4)) + ((k0 & 7) << 1);
                *(uint2*)(smb + OFF_AH + boff) =
                    make_uint2((unsigned)h0 | ((unsigned)h1 << 16),
                               (unsigned)h2 | ((unsigned)h3 << 16));
                *(uint2*)(smb + OFF_AL + boff) =
                    make_uint2((unsigned)l0 | ((unsigned)l1 << 16),
                               (unsigned)l2 | ((unsigned)l3 << 16));
            } else {
                int p = r - 128;
                sXNT[(k0)     * 8 + p] = n0;
                sXNT[(k0 + 1) * 8 + p] = n1;
                sXNT[(k0 + 2) * 8 + p] = n2;
                sXNT[(k0 + 3) * 8 + p] = n3;
            }
        }
        __syncthreads();

        // ============ q GEMM: 4-way contraction split across quarters =======
        {
            ull qa0 = 0, qa1 = 0, qa2 = 0, qa3 = 0;
            const float* xt  = sXNT + (qq * 32) * 8;
            const float* wqp = Wq + (qq * 32) * 128 + jj;
#pragma unroll 8
            for (int ii = 0; ii < 32; ++ii) {
                ulonglong2 xa = *(const ulonglong2*)(xt + ii * 8);
                ulonglong2 xb = *(const ulonglong2*)(xt + ii * 8 + 4);
                ull w = pk2(wqp[ii * 128]);
                ffma2(qa0, xa.x, w); ffma2(qa1, xa.y, w);
                ffma2(qa2, xb.x, w); ffma2(qa3, xb.y, w);
            }
            float2 f0 = upk2(qa0), f1 = upk2(qa1), f2 = upk2(qa2), f3 = upk2(qa3);
            float rr[8] = { f0.x, f0.y, f1.x, f1.y, f2.x, f2.y, f3.x, f3.y };
            if (qq) {
                float* tp = sTMP + (qq - 1) * 1024;
#pragma unroll
                for (int p = 0; p < 8; ++p) tp[p * 128 + jj] = rr[p];
            }
            __syncthreads();
            if (!qq) {
#pragma unroll
                for (int p = 0; p < 8; ++p)
                    sQ[p * 128 + jj] = rr[p] + sTMP[p * 128 + jj]
                                     + sTMP[1024 + p * 128 + jj]
                                     + sTMP[2048 + p * 128 + jj];
            }
            __syncthreads();   // sQ visible before dots
        }

        // ============ kv GEMM: warp tile 64m x 32n, 2 fp16 terms ============
        float acc[4][4][4];
#pragma unroll
        for (int mt = 0; mt < 4; ++mt)
#pragma unroll
            for (int nt = 0; nt < 4; ++nt)
#pragma unroll
                for (int e = 0; e < 4; ++e) acc[mt][nt][e] = 0.0f;

#pragma unroll 1
        for (int t = 0; t < 2; ++t) {
            const unsigned sa = t ? saL : saH;
#pragma unroll
            for (int ks = 0; ks < 8; ++ks) {
                unsigned bfr[2][4];
                unsigned bko = (unsigned)((((ks * 2 + kcb) ^ swb)) << 4);
                ldsm4(bfr[0], sbb + bko);
                ldsm4(bfr[1], sbb + 4096 + bko);
                unsigned ako = (unsigned)((((ks * 2 + kca) ^ swa)) << 4);
#pragma unroll
                for (int mt = 0; mt < 4; ++mt) {
                    unsigned af[4];
                    ldsm4(af, sa + mt * 4096 + ako);
                    mma16816(acc[mt][0], af, &bfr[0][0]);
                    mma16816(acc[mt][1], af, &bfr[0][2]);
                    mma16816(acc[mt][2], af, &bfr[1][0]);
                    mma16816(acc[mt][3], af, &bfr[1][2]);
                }
            }
        }

        // ============ dots from k-fragments (warps with nn<4) ============
        if (is_k) {
#pragma unroll
            for (int mt = 0; mt < 4; ++mt) {
                int p = pbase + mt;
                float d0 = 0.0f, d1 = 0.0f;
#pragma unroll
                for (int nt = 0; nt < 4; ++nt) {
                    float2 qv = *(const float2*)(sQ + p * 128 + head * 32
                                                 + nt * 8 + tig * 2);
                    const float* cc = acc[mt][nt];
                    d0 += cc[0] * qv.x + cc[1] * qv.y;
                    d1 += cc[2] * qv.x + cc[3] * qv.y;
                }
#pragma unroll
                for (int o = 1; o < 4; o <<= 1) {
                    d0 += __shfl_xor_sync(0xffffffffu, d0, o);
                    d1 += __shfl_xor_sync(0xffffffffu, d1, o);
                }
                if (tig == 0) {
                    sDOT[(p * 4 + head) * 16 + gid]     = d0 * SCALE_F;
                    sDOT[(p * 4 + head) * 16 + gid + 8] = d1 * SCALE_F;
                }
            }
        }
        __syncthreads();

        // ============ softmax over m=16 (32 (p,h) rows, warp 0) ============
        if (tid < 32) {
            float* dd = sDOT + tid * 16;
            float mx = dd[0];
#pragma unroll
            for (int m = 1; m < 16; ++m) mx = fmaxf(mx, dd[m]);
            float se = 0.0f;
            float ee[16];
#pragma unroll
            for (int m = 0; m < 16; ++m) { ee[m] = __expf(dd[m] - mx); se += ee[m]; }
            float inv = 1.0f / se;
#pragma unroll
            for (int m = 0; m < 16; ++m) dd[m] = ee[m] * inv;
        }
        __syncthreads();

        // ============ attn * v from v-fragments (warps with nn>=4) ==========
        if (!is_k) {
#pragma unroll
            for (int mt = 0; mt < 4; ++mt) {
                int p = pbase + mt;
                float ag  = sDOT[(p * 4 + head) * 16 + gid];
                float ag8 = sDOT[(p * 4 + head) * 16 + gid + 8];
#pragma unroll
                for (int nt = 0; nt < 4; ++nt) {
                    const float* cc = acc[mt][nt];
                    float o0 = ag * cc[0] + ag8 * cc[2];
                    float o1 = ag * cc[1] + ag8 * cc[3];
#pragma unroll
                    for (int o = 4; o < 32; o <<= 1) {
                        o0 += __shfl_xor_sync(0xffffffffu, o0, o);
                        o1 += __shfl_xor_sync(0xffffffffu, o1, o);
                    }
                    if (gid == 0) {
                        int d0 = nt * 8 + tig * 2;
                        sAOT[(head * 32 + d0) * 8 + p]     = o0;
                        sAOT[(head * 32 + d0 + 1) * 8 + p] = o1;
                    }
                }
            }
        }
        __syncthreads();

        // ============ out GEMM (4-way split) + bias + residual ============
        {
            ull oa0 = 0, oa1 = 0, oa2 = 0, oa3 = 0;
            const float* at  = sAOT + (qq * 32) * 8;
            const float* wop = Wo + (qq * 32) * 128 + jj;
#pragma unroll 8
            for (int ii = 0; ii < 32; ++ii) {
                ulonglong2 xa = *(const ulonglong2*)(at + ii * 8);
                ulonglong2 xb = *(const ulonglong2*)(at + ii * 8 + 4);
                ull w = pk2(wop[ii * 128]);
                ffma2(oa0, xa.x, w); ffma2(oa1, xa.y, w);
                ffma2(oa2, xb.x, w); ffma2(oa3, xb.y, w);
            }
            float2 f0 = upk2(oa0), f1 = upk2(oa1), f2 = upk2(oa2), f3 = upk2(oa3);
            float rr[8] = { f0.x, f0.y, f1.x, f1.y, f2.x, f2.y, f3.x, f3.y };
            if (qq) {
                float* tp = sTMP + (qq - 1) * 1024;
#pragma unroll
                for (int p = 0; p < 8; ++p) tp[p * 128 + jj] = rr[p];
            }
            __syncthreads();
            if (!qq) {
#pragma unroll
                for (int p = 0; p < 8; ++p) {
                    float v = rr[p] + sTMP[p * 128 + jj]
                            + sTMP[1024 + p * 128 + jj]
                            + sTMP[2048 + p * 128 + jj]
                            + sBO[jj] + x[(pt0 + p) * 128 + jj];
                    out[(pt0 + p) * 128 + jj] = v;
                }
            }
            __syncthreads();   // protect sTMP/sQ/sDOT/A tiles before next chunk
        }
    }
}

extern "C" void kernel_launch(void* const* d_in, const int* in_sizes, int n_in,
                              void* d_out, int out_size) {
    const float* x    = (const float*)d_in[0];
    const float* y    = (const float*)d_in[1];
    const float* ln_g = (const float*)d_in[2];
    const float* ln_b = (const float*)d_in[3];
    const float* Wq   = (const float*)d_in[4];
    const float* Wkv  = (const float*)d_in[5];
    const float* Wo   = (const float*)d_in[6];
    const float* bo   = (const float*)d_in[7];
    float* out = (float*)d_out;

    const int P = in_sizes[0] / 128;   // (b*n) points

    int dev = 0;
    cudaGetDevice(&dev);
    int sms = 0;
    cudaDeviceGetAttribute(&sms, cudaDevAttrMultiProcessorCount, dev);
    if (sms <= 0) sms = 148;

    cudaFuncSetAttribute(ca_mma512_kernel,
                         cudaFuncAttributeMaxDynamicSharedMemorySize, SMEM_BYTES);

    ca_mma512_kernel<<<sms, THREADS, SMEM_BYTES>>>(
        x, y, ln_g, ln_b, Wq, Wkv, Wo, bo, out, P);
}